// round 1
// baseline (speedup 1.0000x reference)
#include <cuda_runtime.h>
#include <math.h>

#define LQ   3072
#define DM   1024
#define NH   16
#define HDIM 64
#define SLEN 512
#define NBLK 2
#define DFFN 4096

// ---------------- scratch (no allocation allowed) ----------------
__device__ float g_hx [LQ*DM];
__device__ float g_q  [LQ*DM];
__device__ float g_k  [LQ*DM];
__device__ float g_v  [LQ*DM];
__device__ float g_o  [LQ*DM];
__device__ float g_mid[LQ*DFFN];
__device__ float g_mods[6*DM];
__device__ float g_ck [SLEN*DM];
__device__ float g_cv [SLEN*DM];

// ---------------- adaLN modulation GEMV: out[j] = t . W[j,:] + b[j] ----------------
__global__ void mods_kernel(const float* __restrict__ t, const float* __restrict__ W,
                            const float* __restrict__ b, float* __restrict__ out) {
    int gw   = (blockIdx.x * blockDim.x + threadIdx.x) >> 5;
    int lane = threadIdx.x & 31;
    if (gw >= 6 * DM) return;
    const float* w = W + (size_t)gw * DM;
    float s = 0.f;
    for (int k = lane; k < DM; k += 32) s += t[k] * w[k];
    #pragma unroll
    for (int o = 16; o; o >>= 1) s += __shfl_xor_sync(0xffffffffu, s, o);
    if (lane == 0) out[gw] = s + b[gw];
}

// ---------------- LayerNorm (+ optional scale/shift modulation) ----------------
__global__ void ln_kernel(const float* __restrict__ x, float* __restrict__ out,
                          const float* __restrict__ sc, const float* __restrict__ sh) {
    int row = blockIdx.x;
    const float* xr = x + (size_t)row * DM;
    float s = 0.f, s2 = 0.f;
    for (int c = threadIdx.x; c < DM; c += blockDim.x) {
        float v = xr[c]; s += v; s2 += v * v;
    }
    __shared__ float rs[8], rs2[8];
    int lane = threadIdx.x & 31, wid = threadIdx.x >> 5;
    #pragma unroll
    for (int o = 16; o; o >>= 1) {
        s  += __shfl_xor_sync(0xffffffffu, s,  o);
        s2 += __shfl_xor_sync(0xffffffffu, s2, o);
    }
    if (lane == 0) { rs[wid] = s; rs2[wid] = s2; }
    __syncthreads();
    float ts = 0.f, ts2 = 0.f;
    #pragma unroll
    for (int i = 0; i < 8; i++) { ts += rs[i]; ts2 += rs2[i]; }
    float mean = ts * (1.f / DM);
    float var  = ts2 * (1.f / DM) - mean * mean;
    float rstd = rsqrtf(var + 1e-6f);
    float* orow = out + (size_t)row * DM;
    for (int c = threadIdx.x; c < DM; c += blockDim.x) {
        float v = (xr[c] - mean) * rstd;
        if (sc) v = v * (1.f + sc[c]) + sh[c];
        orow[c] = v;
    }
}

// ---------------- RoPE on q and k (in place) ----------------
__global__ void rope_kernel(float* __restrict__ q, float* __restrict__ k,
                            const float* __restrict__ rope) {
    int idx = blockIdx.x * blockDim.x + threadIdx.x;     // L*H*32
    if (idx >= LQ * NH * 32) return;
    int e = idx & 31;
    int h = (idx >> 5) & (NH - 1);
    int l = idx >> 9;
    float r1 = rope[l * HDIM + e];
    float r2 = rope[l * HDIM + e + 32];
    float c1 = cosf(r1), s1 = sinf(r1);
    float c2 = cosf(r2), s2 = sinf(r2);
    size_t base = (size_t)l * DM + h * HDIM + e;
    float q1 = q[base], q2 = q[base + 32];
    q[base]      = q1 * c1 - q2 * s1;
    q[base + 32] = q2 * c2 + q1 * s2;
    float k1 = k[base], k2 = k[base + 32];
    k[base]      = k1 * c1 - k2 * s1;
    k[base + 32] = k2 * c2 + k1 * s2;
}

// ---------------- SGEMM: C[M,N] = A[M,K] @ W[N,K]^T (+bias, +epilogue) ----------------
// epi: 0 = store, 1 = exact GELU, 2 = C += gate*(val)   (gate may be null => 1)
__global__ __launch_bounds__(256) void sgemm_kernel(
    int M, int N, int K,
    const float* __restrict__ A, const float* __restrict__ W,
    const float* __restrict__ bias, float* __restrict__ C,
    int epi, const float* __restrict__ gate) {
    __shared__ float As[8][128];
    __shared__ float Bs[8][128];
    int tid = threadIdx.x;
    int m0 = blockIdx.y * 128, n0 = blockIdx.x * 128;
    int ty = tid >> 4, tx = tid & 15;
    int lr = tid >> 1, lc = (tid & 1) * 4;
    const float* Ap = A + (size_t)(m0 + lr) * K + lc;
    const float* Wp = W + (size_t)(n0 + lr) * K + lc;
    float acc[8][8];
    #pragma unroll
    for (int i = 0; i < 8; i++)
        #pragma unroll
        for (int j = 0; j < 8; j++) acc[i][j] = 0.f;

    for (int k0 = 0; k0 < K; k0 += 8) {
        float4 av = *(const float4*)(Ap + k0);
        float4 bv = *(const float4*)(Wp + k0);
        As[lc + 0][lr] = av.x; As[lc + 1][lr] = av.y;
        As[lc + 2][lr] = av.z; As[lc + 3][lr] = av.w;
        Bs[lc + 0][lr] = bv.x; Bs[lc + 1][lr] = bv.y;
        Bs[lc + 2][lr] = bv.z; Bs[lc + 3][lr] = bv.w;
        __syncthreads();
        #pragma unroll
        for (int kk = 0; kk < 8; kk++) {
            float a[8], b[8];
            *(float4*)(a)     = *(const float4*)(&As[kk][ty * 8]);
            *(float4*)(a + 4) = *(const float4*)(&As[kk][ty * 8 + 4]);
            *(float4*)(b)     = *(const float4*)(&Bs[kk][tx * 8]);
            *(float4*)(b + 4) = *(const float4*)(&Bs[kk][tx * 8 + 4]);
            #pragma unroll
            for (int i = 0; i < 8; i++)
                #pragma unroll
                for (int j = 0; j < 8; j++)
                    acc[i][j] += a[i] * b[j];
        }
        __syncthreads();
    }

    #pragma unroll
    for (int i = 0; i < 8; i++) {
        int row = m0 + ty * 8 + i;
        #pragma unroll
        for (int j = 0; j < 8; j++) {
            int col = n0 + tx * 8 + j;
            float val = acc[i][j];
            if (bias) val += bias[col];
            size_t idx = (size_t)row * N + col;
            if (epi == 0) {
                C[idx] = val;
            } else if (epi == 1) {
                C[idx] = 0.5f * val * (1.f + erff(val * 0.70710678118654752f));
            } else {
                float g = gate ? gate[col] : 1.f;
                C[idx] += g * val;
            }
        }
    }
}

// ---------------- flash attention (non-causal, hd=64) ----------------
// grid: (Lq/64, H). 256 threads; thread t handles row r=t/4, dim slice (t%4)*16.
#define SPITCH 65
__global__ __launch_bounds__(256) void attn_kernel(
    const float* __restrict__ Q, const float* __restrict__ K,
    const float* __restrict__ V, float* __restrict__ O,
    int Lk, float scale) {
    extern __shared__ float sm[];
    float* Qs = sm;
    float* Ks = sm + 64 * SPITCH;
    float* Vs = sm + 2 * 64 * SPITCH;
    float* Ps = sm + 3 * 64 * SPITCH;

    int t  = threadIdx.x;
    int r  = t >> 2;
    int cg = t & 3;
    int h  = blockIdx.y;
    int q0 = blockIdx.x * 64;

    #pragma unroll
    for (int it = 0; it < 16; it++) {
        int idx = it * 256 + t;
        int row = idx >> 6, col = idx & 63;
        Qs[row * SPITCH + col] = Q[(size_t)(q0 + row) * DM + h * HDIM + col];
    }
    float m = -1e30f, l = 0.f;
    float o[16];
    #pragma unroll
    for (int i = 0; i < 16; i++) o[i] = 0.f;
    __syncthreads();

    for (int kv0 = 0; kv0 < Lk; kv0 += 64) {
        #pragma unroll
        for (int it = 0; it < 16; it++) {
            int idx = it * 256 + t;
            int row = idx >> 6, col = idx & 63;
            Ks[row * SPITCH + col] = K[(size_t)(kv0 + row) * DM + h * HDIM + col];
            Vs[row * SPITCH + col] = V[(size_t)(kv0 + row) * DM + h * HDIM + col];
        }
        __syncthreads();

        float s[16];
        #pragma unroll
        for (int jj = 0; jj < 16; jj++) s[jj] = 0.f;
        const float* qrow = &Qs[r * SPITCH];
        #pragma unroll 4
        for (int d = 0; d < 64; d++) {
            float qd = qrow[d];
            #pragma unroll
            for (int jj = 0; jj < 16; jj++)
                s[jj] += qd * Ks[(cg * 16 + jj) * SPITCH + d];
        }
        float mloc = -1e30f;
        #pragma unroll
        for (int jj = 0; jj < 16; jj++) {
            s[jj] *= scale;
            mloc = fmaxf(mloc, s[jj]);
        }
        mloc = fmaxf(mloc, __shfl_xor_sync(0xffffffffu, mloc, 1));
        mloc = fmaxf(mloc, __shfl_xor_sync(0xffffffffu, mloc, 2));
        float mnew = fmaxf(m, mloc);
        float corr = expf(m - mnew);
        float lloc = 0.f;
        #pragma unroll
        for (int jj = 0; jj < 16; jj++) {
            float p = expf(s[jj] - mnew);
            Ps[r * SPITCH + cg * 16 + jj] = p;
            lloc += p;
        }
        lloc += __shfl_xor_sync(0xffffffffu, lloc, 1);
        lloc += __shfl_xor_sync(0xffffffffu, lloc, 2);
        l = l * corr + lloc;
        m = mnew;
        #pragma unroll
        for (int dd = 0; dd < 16; dd++) o[dd] *= corr;
        __syncwarp();
        #pragma unroll 4
        for (int j = 0; j < 64; j++) {
            float p = Ps[r * SPITCH + j];
            #pragma unroll
            for (int dd = 0; dd < 16; dd++)
                o[dd] += p * Vs[j * SPITCH + cg * 16 + dd];
        }
        __syncthreads();
    }
    float inv = 1.f / l;
    #pragma unroll
    for (int dd = 0; dd < 16; dd++)
        O[(size_t)(q0 + r) * DM + h * HDIM + cg * 16 + dd] = o[dd] * inv;
}

// ---------------- host orchestration ----------------
extern "C" void kernel_launch(void* const* d_in, const int* in_sizes, int n_in,
                              void* d_out, int out_size) {
    const float* x    = (const float*)d_in[0];
    const float* temb = (const float*)d_in[1];
    const float* ctx  = (const float*)d_in[2];
    const float* rope = (const float*)d_in[3];
    const float* adaW = (const float*)d_in[4];
    const float* adab = (const float*)d_in[5];
    const float* sqW  = (const float*)d_in[6];
    const float* skW  = (const float*)d_in[7];
    const float* svW  = (const float*)d_in[8];
    const float* soW  = (const float*)d_in[9];
    const float* sob  = (const float*)d_in[10];
    const float* cqW  = (const float*)d_in[11];
    const float* ckW  = (const float*)d_in[12];
    const float* cvW  = (const float*)d_in[13];
    const float* coW  = (const float*)d_in[14];
    const float* cob  = (const float*)d_in[15];
    const float* f1W  = (const float*)d_in[16];
    const float* f1b  = (const float*)d_in[17];
    const float* f2W  = (const float*)d_in[18];
    const float* f2b  = (const float*)d_in[19];
    float* xo = (float*)d_out;

    float *hx, *q, *k, *v, *o, *mid, *mods, *ck, *cv;
    cudaGetSymbolAddress((void**)&hx,   g_hx);
    cudaGetSymbolAddress((void**)&q,    g_q);
    cudaGetSymbolAddress((void**)&k,    g_k);
    cudaGetSymbolAddress((void**)&v,    g_v);
    cudaGetSymbolAddress((void**)&o,    g_o);
    cudaGetSymbolAddress((void**)&mid,  g_mid);
    cudaGetSymbolAddress((void**)&mods, g_mods);
    cudaGetSymbolAddress((void**)&ck,   g_ck);
    cudaGetSymbolAddress((void**)&cv,   g_cv);

    const int SMEMA = 4 * 64 * SPITCH * (int)sizeof(float);
    cudaFuncSetAttribute(attn_kernel, cudaFuncAttributeMaxDynamicSharedMemorySize, SMEMA);

    cudaMemcpyAsync(xo, x, sizeof(float) * LQ * DM, cudaMemcpyDeviceToDevice);

    dim3 gD (DM / 128,   LQ / 128);    // 3072x1024
    dim3 gC (DM / 128,   SLEN / 128);  // 512x1024
    dim3 gF1(DFFN / 128, LQ / 128);    // 3072x4096
    dim3 gA (LQ / 64, NH);

    for (int i = 0; i < NBLK; i++) {
        const float* adaWi = adaW + (size_t)i * 6 * DM * DM;
        const float* adabi = adab + (size_t)i * 6 * DM;
        const float* sqWi  = sqW  + (size_t)i * DM * DM;
        const float* skWi  = skW  + (size_t)i * DM * DM;
        const float* svWi  = svW  + (size_t)i * DM * DM;
        const float* soWi  = soW  + (size_t)i * DM * DM;
        const float* sobi  = sob  + (size_t)i * DM;
        const float* cqWi  = cqW  + (size_t)i * DM * DM;
        const float* ckWi  = ckW  + (size_t)i * DM * DM;
        const float* cvWi  = cvW  + (size_t)i * DM * DM;
        const float* coWi  = coW  + (size_t)i * DM * DM;
        const float* cobi  = cob  + (size_t)i * DM;
        const float* f1Wi  = f1W  + (size_t)i * DFFN * DM;
        const float* f1bi  = f1b  + (size_t)i * DFFN;
        const float* f2Wi  = f2W  + (size_t)i * DM * DFFN;
        const float* f2bi  = f2b  + (size_t)i * DM;

        // adaLN mods
        mods_kernel<<<(6 * DM * 32 + 255) / 256, 256>>>(temb, adaWi, adabi, mods);
        // self-attn branch
        ln_kernel<<<LQ, 256>>>(xo, hx, mods + DM, mods);
        sgemm_kernel<<<gD, 256>>>(LQ, DM, DM, hx, sqWi, nullptr, q, 0, nullptr);
        sgemm_kernel<<<gD, 256>>>(LQ, DM, DM, hx, skWi, nullptr, k, 0, nullptr);
        sgemm_kernel<<<gD, 256>>>(LQ, DM, DM, hx, svWi, nullptr, v, 0, nullptr);
        rope_kernel<<<(LQ * NH * 32 + 255) / 256, 256>>>(q, k, rope);
        attn_kernel<<<gA, 256, SMEMA>>>(q, k, v, o, LQ, 0.125f);
        sgemm_kernel<<<gD, 256>>>(LQ, DM, DM, o, soWi, sobi, xo, 2, mods + 2 * DM);
        // cross-attn branch
        ln_kernel<<<LQ, 256>>>(xo, hx, nullptr, nullptr);
        sgemm_kernel<<<gD, 256>>>(LQ, DM, DM, hx, cqWi, nullptr, q, 0, nullptr);
        sgemm_kernel<<<gC, 256>>>(SLEN, DM, DM, ctx, ckWi, nullptr, ck, 0, nullptr);
        sgemm_kernel<<<gC, 256>>>(SLEN, DM, DM, ctx, cvWi, nullptr, cv, 0, nullptr);
        attn_kernel<<<gA, 256, SMEMA>>>(q, ck, cv, o, SLEN, 0.125f);
        sgemm_kernel<<<gD, 256>>>(LQ, DM, DM, o, coWi, cobi, xo, 2, nullptr);
        // MLP branch
        ln_kernel<<<LQ, 256>>>(xo, hx, mods + 4 * DM, mods + 3 * DM);
        sgemm_kernel<<<gF1, 256>>>(LQ, DFFN, DM, hx, f1Wi, f1bi, mid, 1, nullptr);
        sgemm_kernel<<<gD, 256>>>(LQ, DM, DFFN, mid, f2Wi, f2bi, xo, 2, mods + 5 * DM);
    }
}

// round 3
// speedup vs baseline: 6.1032x; 6.1032x over previous
#include <cuda_runtime.h>
#include <math.h>
#include <stdint.h>

#define LQ   3072
#define DM   1024
#define NH   16
#define HDIM 64
#define SLEN 512
#define NBLK 2
#define DFFN 4096

// ---------------- scratch (no allocation allowed) ----------------
__device__ float g_hx [LQ*DM];
__device__ float g_q  [LQ*DM];
__device__ float g_k  [LQ*DM];
__device__ float g_v  [LQ*DM];
__device__ float g_o  [LQ*DM];
__device__ float g_mid[LQ*DFFN];
__device__ float g_mods[6*DM];
__device__ float g_ck [SLEN*DM];
__device__ float g_cv [SLEN*DM];

// ---------------- helpers ----------------
__device__ __forceinline__ uint32_t f2tf(float x) {
    uint32_t r;
    asm("cvt.rna.tf32.f32 %0, %1;" : "=r"(r) : "f"(x));
    return r;
}
__device__ __forceinline__ uint32_t sptr(const void* p) {
    return (uint32_t)__cvta_generic_to_shared(p);
}
#define CPA16(dst, src) asm volatile("cp.async.cg.shared.global [%0],[%1],16;" :: "r"(dst), "l"(src))
#define CPCOMMIT()      asm volatile("cp.async.commit_group;")

__device__ __forceinline__ void mma_tf32(float* c, const uint32_t* a, uint32_t b0, uint32_t b1) {
    asm volatile(
        "mma.sync.aligned.m16n8k8.row.col.f32.tf32.tf32.f32 "
        "{%0,%1,%2,%3},{%4,%5,%6,%7},{%8,%9},{%0,%1,%2,%3};"
        : "+f"(c[0]), "+f"(c[1]), "+f"(c[2]), "+f"(c[3])
        : "r"(a[0]), "r"(a[1]), "r"(a[2]), "r"(a[3]), "r"(b0), "r"(b1));
}

// ---------------- adaLN modulation GEMV ----------------
__global__ void mods_kernel(const float* __restrict__ t, const float* __restrict__ W,
                            const float* __restrict__ b, float* __restrict__ out) {
    int gw   = (blockIdx.x * blockDim.x + threadIdx.x) >> 5;
    int lane = threadIdx.x & 31;
    if (gw >= 6 * DM) return;
    const float* w = W + (size_t)gw * DM;
    float s = 0.f;
    for (int k = lane; k < DM; k += 32) s += t[k] * w[k];
    #pragma unroll
    for (int o = 16; o; o >>= 1) s += __shfl_xor_sync(0xffffffffu, s, o);
    if (lane == 0) out[gw] = s + b[gw];
}

// ---------------- LayerNorm (+ optional scale/shift modulation) ----------------
__global__ void ln_kernel(const float* __restrict__ x, float* __restrict__ out,
                          const float* __restrict__ sc, const float* __restrict__ sh) {
    int row = blockIdx.x;
    const float* xr = x + (size_t)row * DM;
    float s = 0.f, s2 = 0.f;
    for (int c = threadIdx.x; c < DM; c += blockDim.x) {
        float v = xr[c]; s += v; s2 += v * v;
    }
    __shared__ float rs[8], rs2[8];
    int lane = threadIdx.x & 31, wid = threadIdx.x >> 5;
    #pragma unroll
    for (int o = 16; o; o >>= 1) {
        s  += __shfl_xor_sync(0xffffffffu, s,  o);
        s2 += __shfl_xor_sync(0xffffffffu, s2, o);
    }
    if (lane == 0) { rs[wid] = s; rs2[wid] = s2; }
    __syncthreads();
    float ts = 0.f, ts2 = 0.f;
    #pragma unroll
    for (int i = 0; i < 8; i++) { ts += rs[i]; ts2 += rs2[i]; }
    float mean = ts * (1.f / DM);
    float var  = ts2 * (1.f / DM) - mean * mean;
    float rstd = rsqrtf(var + 1e-6f);
    float* orow = out + (size_t)row * DM;
    for (int c = threadIdx.x; c < DM; c += blockDim.x) {
        float v = (xr[c] - mean) * rstd;
        if (sc) v = v * (1.f + sc[c]) + sh[c];
        orow[c] = v;
    }
}

// ---------------- RoPE on q and k (in place) ----------------
__global__ void rope_kernel(float* __restrict__ q, float* __restrict__ k,
                            const float* __restrict__ rope) {
    int idx = blockIdx.x * blockDim.x + threadIdx.x;
    if (idx >= LQ * NH * 32) return;
    int e = idx & 31;
    int h = (idx >> 5) & (NH - 1);
    int l = idx >> 9;
    float r1 = rope[l * HDIM + e];
    float r2 = rope[l * HDIM + e + 32];
    float c1 = cosf(r1), s1 = sinf(r1);
    float c2 = cosf(r2), s2 = sinf(r2);
    size_t base = (size_t)l * DM + h * HDIM + e;
    float q1 = q[base], q2 = q[base + 32];
    q[base]      = q1 * c1 - q2 * s1;
    q[base + 32] = q2 * c2 + q1 * s2;
    float k1 = k[base], k2 = k[base + 32];
    k[base]      = k1 * c1 - k2 * s1;
    k[base + 32] = k2 * c2 + k1 * s2;
}

// ---------------- tf32 tensor-core GEMM ----------------
// C[M,N] = A[M,K] @ W[N,K]^T, 128x128x32 tiles, double-buffered cp.async
// epi: 0 = store, 1 = exact GELU, 2 = C += gate*(val+bias)
#define GP 36   // smem pitch (floats) for 32-wide K tile

__device__ __forceinline__ void cp_tile128(const float* G, int ldg, int row0, int k0,
                                           float* S, int tid) {
    #pragma unroll
    for (int i = 0; i < 4; i++) {
        int id = tid + i * 256;
        int r = id >> 3, c4 = id & 7;
        CPA16(sptr(&S[r * GP + c4 * 4]), G + (size_t)(row0 + r) * ldg + k0 + c4 * 4);
    }
}

__global__ __launch_bounds__(256, 2) void gemm_tf32(
    int M, int N, int K,
    const float* __restrict__ A, const float* __restrict__ W,
    const float* __restrict__ bias, float* __restrict__ C,
    int epi, const float* __restrict__ gate) {
    extern __shared__ float sm[];
    float* As = sm;                    // 2 * 128 * GP
    float* Bs = sm + 2 * 128 * GP;     // 2 * 128 * GP
    int tid = threadIdx.x, wid = tid >> 5, lane = tid & 31;
    int tr = lane >> 2, tc = lane & 3;
    int m0 = blockIdx.y * 128, n0 = blockIdx.x * 128;
    int wm = (wid >> 2) * 64, wn = (wid & 3) * 32;

    float c[4][4][4];
    #pragma unroll
    for (int a = 0; a < 4; a++)
        #pragma unroll
        for (int b = 0; b < 4; b++)
            #pragma unroll
            for (int d = 0; d < 4; d++) c[a][b][d] = 0.f;

    int ntile = K / 32;
    cp_tile128(A, K, m0, 0, As, tid);
    cp_tile128(W, K, n0, 0, Bs, tid);
    CPCOMMIT();

    for (int kt = 0; kt < ntile; kt++) {
        if (kt + 1 < ntile) {
            cp_tile128(A, K, m0, (kt + 1) * 32, As + ((kt + 1) & 1) * 128 * GP, tid);
            cp_tile128(W, K, n0, (kt + 1) * 32, Bs + ((kt + 1) & 1) * 128 * GP, tid);
            CPCOMMIT();
            asm volatile("cp.async.wait_group 1;");
        } else {
            asm volatile("cp.async.wait_group 0;");
        }
        __syncthreads();
        const float* Ab = As + (kt & 1) * 128 * GP;
        const float* Bb = Bs + (kt & 1) * 128 * GP;
        #pragma unroll
        for (int ks = 0; ks < 4; ks++) {
            uint32_t af[4][4];
            #pragma unroll
            for (int mt = 0; mt < 4; mt++) {
                const float* ap = Ab + (wm + mt * 16) * GP + ks * 8;
                af[mt][0] = f2tf(ap[tr * GP + tc]);
                af[mt][1] = f2tf(ap[(tr + 8) * GP + tc]);
                af[mt][2] = f2tf(ap[tr * GP + tc + 4]);
                af[mt][3] = f2tf(ap[(tr + 8) * GP + tc + 4]);
            }
            #pragma unroll
            for (int nn = 0; nn < 4; nn++) {
                const float* bp = Bb + (wn + nn * 8) * GP + ks * 8;
                uint32_t b0 = f2tf(bp[tr * GP + tc]);
                uint32_t b1 = f2tf(bp[tr * GP + tc + 4]);
                #pragma unroll
                for (int mt = 0; mt < 4; mt++)
                    mma_tf32(c[mt][nn], af[mt], b0, b1);
            }
        }
        __syncthreads();
    }

    // epilogue
    #pragma unroll
    for (int mt = 0; mt < 4; mt++) {
        int r0 = m0 + wm + mt * 16 + tr;
        int r1 = r0 + 8;
        #pragma unroll
        for (int nn = 0; nn < 4; nn++) {
            int col = n0 + wn + nn * 8 + 2 * tc;
            float b0v = bias ? bias[col] : 0.f;
            float b1v = bias ? bias[col + 1] : 0.f;
            float v00 = c[mt][nn][0] + b0v, v01 = c[mt][nn][1] + b1v;
            float v10 = c[mt][nn][2] + b0v, v11 = c[mt][nn][3] + b1v;
            size_t i0 = (size_t)r0 * N + col;
            size_t i1 = (size_t)r1 * N + col;
            if (epi == 0) {
                C[i0] = v00; C[i0 + 1] = v01;
                C[i1] = v10; C[i1 + 1] = v11;
            } else if (epi == 1) {
                const float k = 0.70710678118654752f;
                C[i0]     = 0.5f * v00 * (1.f + erff(v00 * k));
                C[i0 + 1] = 0.5f * v01 * (1.f + erff(v01 * k));
                C[i1]     = 0.5f * v10 * (1.f + erff(v10 * k));
                C[i1 + 1] = 0.5f * v11 * (1.f + erff(v11 * k));
            } else {
                float g0 = gate ? gate[col] : 1.f;
                float g1 = gate ? gate[col + 1] : 1.f;
                C[i0]     += g0 * v00; C[i0 + 1] += g1 * v01;
                C[i1]     += g0 * v10; C[i1 + 1] += g1 * v11;
            }
        }
    }
}

// ---------------- tf32 tensor-core flash attention ----------------
// 64 q-rows per block, 4 warps (16 q-rows each), hd=64, kv tile 64.
#define AP 68
__global__ __launch_bounds__(128, 3) void attn_mma(
    const float* __restrict__ Q, const float* __restrict__ K,
    const float* __restrict__ V, float* __restrict__ O,
    int Lk, float scale) {
    extern __shared__ float sm[];
    float* Qs = sm;
    float* Ks = Qs + 64 * AP;
    float* Vs = Ks + 64 * AP;
    float* Ps = Vs + 64 * AP;

    int tid = threadIdx.x, wid = tid >> 5, lane = tid & 31;
    int tr = lane >> 2, tc = lane & 3;
    int h = blockIdx.y, q0 = blockIdx.x * 64;
    const float* Qg = Q + (size_t)q0 * DM + h * HDIM;

    #pragma unroll
    for (int i = 0; i < 8; i++) {
        int id = tid + i * 128;
        int r = id >> 4, c4 = id & 15;
        CPA16(sptr(&Qs[r * AP + c4 * 4]), Qg + (size_t)r * DM + c4 * 4);
    }
    CPCOMMIT();
    asm volatile("cp.async.wait_group 0;");
    __syncthreads();

    // Q fragments (pre-scaled), held in registers across the KV loop
    uint32_t qf[8][4];
    #pragma unroll
    for (int ks = 0; ks < 8; ks++) {
        const float* qp = Qs + (wid * 16) * AP + ks * 8;
        qf[ks][0] = f2tf(qp[tr * AP + tc] * scale);
        qf[ks][1] = f2tf(qp[(tr + 8) * AP + tc] * scale);
        qf[ks][2] = f2tf(qp[tr * AP + tc + 4] * scale);
        qf[ks][3] = f2tf(qp[(tr + 8) * AP + tc + 4] * scale);
    }
    __syncthreads();   // Qs no longer needed; (kept separate, no reuse anyway)

    float mv0 = -1e30f, mv1 = -1e30f, l0 = 0.f, l1 = 0.f;
    float o[8][4];
    #pragma unroll
    for (int nt = 0; nt < 8; nt++)
        #pragma unroll
        for (int d = 0; d < 4; d++) o[nt][d] = 0.f;

    for (int kv0 = 0; kv0 < Lk; kv0 += 64) {
        #pragma unroll
        for (int i = 0; i < 8; i++) {
            int id = tid + i * 128;
            int r = id >> 4, c4 = id & 15;
            const float* kg = K + (size_t)(kv0 + r) * DM + h * HDIM + c4 * 4;
            const float* vg = V + (size_t)(kv0 + r) * DM + h * HDIM + c4 * 4;
            CPA16(sptr(&Ks[r * AP + c4 * 4]), kg);
            CPA16(sptr(&Vs[r * AP + c4 * 4]), vg);
        }
        CPCOMMIT();
        asm volatile("cp.async.wait_group 0;");
        __syncthreads();

        // S = (Q*scale) @ K^T
        float s[8][4];
        #pragma unroll
        for (int nt = 0; nt < 8; nt++)
            #pragma unroll
            for (int d = 0; d < 4; d++) s[nt][d] = 0.f;
        #pragma unroll
        for (int ks = 0; ks < 8; ks++) {
            #pragma unroll
            for (int nt = 0; nt < 8; nt++) {
                uint32_t b0 = f2tf(Ks[(nt * 8 + tr) * AP + ks * 8 + tc]);
                uint32_t b1 = f2tf(Ks[(nt * 8 + tr) * AP + ks * 8 + tc + 4]);
                mma_tf32(s[nt], qf[ks], b0, b1);
            }
        }

        // online softmax (rows tr and tr+8 of this warp's 16)
        float ml0 = -1e30f, ml1 = -1e30f;
        #pragma unroll
        for (int nt = 0; nt < 8; nt++) {
            ml0 = fmaxf(ml0, fmaxf(s[nt][0], s[nt][1]));
            ml1 = fmaxf(ml1, fmaxf(s[nt][2], s[nt][3]));
        }
        ml0 = fmaxf(ml0, __shfl_xor_sync(0xffffffffu, ml0, 1));
        ml0 = fmaxf(ml0, __shfl_xor_sync(0xffffffffu, ml0, 2));
        ml1 = fmaxf(ml1, __shfl_xor_sync(0xffffffffu, ml1, 1));
        ml1 = fmaxf(ml1, __shfl_xor_sync(0xffffffffu, ml1, 2));
        float mn0 = fmaxf(mv0, ml0), mn1 = fmaxf(mv1, ml1);
        float cr0 = __expf(mv0 - mn0), cr1 = __expf(mv1 - mn1);
        float ls0 = 0.f, ls1 = 0.f;
        float* prow0 = &Ps[(wid * 16 + tr) * AP];
        float* prow1 = &Ps[(wid * 16 + tr + 8) * AP];
        #pragma unroll
        for (int nt = 0; nt < 8; nt++) {
            float p0 = __expf(s[nt][0] - mn0);
            float p1 = __expf(s[nt][1] - mn0);
            float p2 = __expf(s[nt][2] - mn1);
            float p3 = __expf(s[nt][3] - mn1);
            ls0 += p0 + p1; ls1 += p2 + p3;
            *(float2*)&prow0[nt * 8 + 2 * tc] = make_float2(p0, p1);
            *(float2*)&prow1[nt * 8 + 2 * tc] = make_float2(p2, p3);
        }
        ls0 += __shfl_xor_sync(0xffffffffu, ls0, 1);
        ls0 += __shfl_xor_sync(0xffffffffu, ls0, 2);
        ls1 += __shfl_xor_sync(0xffffffffu, ls1, 1);
        ls1 += __shfl_xor_sync(0xffffffffu, ls1, 2);
        l0 = l0 * cr0 + ls0;
        l1 = l1 * cr1 + ls1;
        mv0 = mn0; mv1 = mn1;
        #pragma unroll
        for (int nt = 0; nt < 8; nt++) {
            o[nt][0] *= cr0; o[nt][1] *= cr0;
            o[nt][2] *= cr1; o[nt][3] *= cr1;
        }
        __syncwarp();

        // O += P @ V
        #pragma unroll
        for (int ks = 0; ks < 8; ks++) {
            uint32_t af[4];
            const float* pp = Ps + (wid * 16) * AP + ks * 8;
            af[0] = f2tf(pp[tr * AP + tc]);
            af[1] = f2tf(pp[(tr + 8) * AP + tc]);
            af[2] = f2tf(pp[tr * AP + tc + 4]);
            af[3] = f2tf(pp[(tr + 8) * AP + tc + 4]);
            #pragma unroll
            for (int nt = 0; nt < 8; nt++) {
                uint32_t b0 = f2tf(Vs[(ks * 8 + tc) * AP + nt * 8 + tr]);
                uint32_t b1 = f2tf(Vs[(ks * 8 + tc + 4) * AP + nt * 8 + tr]);
                mma_tf32(o[nt], af, b0, b1);
            }
        }
        __syncthreads();
    }

    float i0 = 1.f / l0, i1 = 1.f / l1;
    float* og0 = O + (size_t)(q0 + wid * 16 + tr) * DM + h * HDIM;
    float* og1 = O + (size_t)(q0 + wid * 16 + tr + 8) * DM + h * HDIM;
    #pragma unroll
    for (int nt = 0; nt < 8; nt++) {
        *(float2*)&og0[nt * 8 + 2 * tc] = make_float2(o[nt][0] * i0, o[nt][1] * i0);
        *(float2*)&og1[nt * 8 + 2 * tc] = make_float2(o[nt][2] * i1, o[nt][3] * i1);
    }
}

// ---------------- host orchestration ----------------
extern "C" void kernel_launch(void* const* d_in, const int* in_sizes, int n_in,
                              void* d_out, int out_size) {
    const float* x    = (const float*)d_in[0];
    const float* temb = (const float*)d_in[1];
    const float* ctx  = (const float*)d_in[2];
    const float* rope = (const float*)d_in[3];
    const float* adaW = (const float*)d_in[4];
    const float* adab = (const float*)d_in[5];
    const float* sqW  = (const float*)d_in[6];
    const float* skW  = (const float*)d_in[7];
    const float* svW  = (const float*)d_in[8];
    const float* soW  = (const float*)d_in[9];
    const float* sob  = (const float*)d_in[10];
    const float* cqW  = (const float*)d_in[11];
    const float* ckW  = (const float*)d_in[12];
    const float* cvW  = (const float*)d_in[13];
    const float* coW  = (const float*)d_in[14];
    const float* cob  = (const float*)d_in[15];
    const float* f1W  = (const float*)d_in[16];
    const float* f1b  = (const float*)d_in[17];
    const float* f2W  = (const float*)d_in[18];
    const float* f2b  = (const float*)d_in[19];
    float* xo = (float*)d_out;

    float *hx, *q, *k, *v, *o, *mid, *mods, *ck, *cv;
    cudaGetSymbolAddress((void**)&hx,   g_hx);
    cudaGetSymbolAddress((void**)&q,    g_q);
    cudaGetSymbolAddress((void**)&k,    g_k);
    cudaGetSymbolAddress((void**)&v,    g_v);
    cudaGetSymbolAddress((void**)&o,    g_o);
    cudaGetSymbolAddress((void**)&mid,  g_mid);
    cudaGetSymbolAddress((void**)&mods, g_mods);
    cudaGetSymbolAddress((void**)&ck,   g_ck);
    cudaGetSymbolAddress((void**)&cv,   g_cv);

    const int GEMM_SMEM = 2 * 2 * 128 * GP * (int)sizeof(float);   // 73728
    const int ATTN_SMEM = 4 * 64 * AP * (int)sizeof(float);        // 69632
    cudaFuncSetAttribute(gemm_tf32, cudaFuncAttributeMaxDynamicSharedMemorySize, GEMM_SMEM);
    cudaFuncSetAttribute(attn_mma,  cudaFuncAttributeMaxDynamicSharedMemorySize, ATTN_SMEM);

    cudaMemcpyAsync(xo, x, sizeof(float) * LQ * DM, cudaMemcpyDeviceToDevice);

    dim3 gD (DM / 128,   LQ / 128);
    dim3 gC (DM / 128,   SLEN / 128);
    dim3 gF1(DFFN / 128, LQ / 128);
    dim3 gA (LQ / 64, NH);

    for (int i = 0; i < NBLK; i++) {
        const float* adaWi = adaW + (size_t)i * 6 * DM * DM;
        const float* adabi = adab + (size_t)i * 6 * DM;
        const float* sqWi  = sqW  + (size_t)i * DM * DM;
        const float* skWi  = skW  + (size_t)i * DM * DM;
        const float* svWi  = svW  + (size_t)i * DM * DM;
        const float* soWi  = soW  + (size_t)i * DM * DM;
        const float* sobi  = sob  + (size_t)i * DM;
        const float* cqWi  = cqW  + (size_t)i * DM * DM;
        const float* ckWi  = ckW  + (size_t)i * DM * DM;
        const float* cvWi  = cvW  + (size_t)i * DM * DM;
        const float* coWi  = coW  + (size_t)i * DM * DM;
        const float* cobi  = cob  + (size_t)i * DM;
        const float* f1Wi  = f1W  + (size_t)i * DFFN * DM;
        const float* f1bi  = f1b  + (size_t)i * DFFN;
        const float* f2Wi  = f2W  + (size_t)i * DM * DFFN;
        const float* f2bi  = f2b  + (size_t)i * DM;

        // adaLN mods
        mods_kernel<<<(6 * DM * 32 + 255) / 256, 256>>>(temb, adaWi, adabi, mods);
        // self-attn branch
        ln_kernel<<<LQ, 256>>>(xo, hx, mods + DM, mods);
        gemm_tf32<<<gD, 256, GEMM_SMEM>>>(LQ, DM, DM, hx, sqWi, nullptr, q, 0, nullptr);
        gemm_tf32<<<gD, 256, GEMM_SMEM>>>(LQ, DM, DM, hx, skWi, nullptr, k, 0, nullptr);
        gemm_tf32<<<gD, 256, GEMM_SMEM>>>(LQ, DM, DM, hx, svWi, nullptr, v, 0, nullptr);
        rope_kernel<<<(LQ * NH * 32 + 255) / 256, 256>>>(q, k, rope);
        attn_mma<<<gA, 128, ATTN_SMEM>>>(q, k, v, o, LQ, 0.125f);
        gemm_tf32<<<gD, 256, GEMM_SMEM>>>(LQ, DM, DM, o, soWi, sobi, xo, 2, mods + 2 * DM);
        // cross-attn branch
        ln_kernel<<<LQ, 256>>>(xo, hx, nullptr, nullptr);
        gemm_tf32<<<gD, 256, GEMM_SMEM>>>(LQ, DM, DM, hx, cqWi, nullptr, q, 0, nullptr);
        gemm_tf32<<<gC, 256, GEMM_SMEM>>>(SLEN, DM, DM, ctx, ckWi, nullptr, ck, 0, nullptr);
        gemm_tf32<<<gC, 256, GEMM_SMEM>>>(SLEN, DM, DM, ctx, cvWi, nullptr, cv, 0, nullptr);
        attn_mma<<<gA, 128, ATTN_SMEM>>>(q, ck, cv, o, SLEN, 0.125f);
        gemm_tf32<<<gD, 256, GEMM_SMEM>>>(LQ, DM, DM, o, coWi, cobi, xo, 2, nullptr);
        // MLP branch
        ln_kernel<<<LQ, 256>>>(xo, hx, mods + 4 * DM, mods + 3 * DM);
        gemm_tf32<<<gF1, 256, GEMM_SMEM>>>(LQ, DFFN, DM, hx, f1Wi, f1bi, mid, 1, nullptr);
        gemm_tf32<<<gD, 256, GEMM_SMEM>>>(LQ, DM, DFFN, mid, f2Wi, f2bi, xo, 2, mods + 5 * DM);
    }
}

// round 9
// speedup vs baseline: 6.4845x; 1.0625x over previous
#include <cuda_runtime.h>
#include <math.h>
#include <stdint.h>

#define LQ   3072
#define DM   1024
#define NH   16
#define HDIM 64
#define SLEN 512
#define NBLK 2
#define DFFN 4096

// ---------------- scratch (no allocation allowed) ----------------
__device__ float g_hx [LQ*DM];
__device__ float g_q  [LQ*DM];
__device__ float g_k  [LQ*DM];
__device__ float g_v  [LQ*DM];
__device__ float g_o  [LQ*DM];
__device__ float g_mid[LQ*DFFN];
__device__ float g_mods[6*DM];
__device__ float g_ck [SLEN*DM];
__device__ float g_cv [SLEN*DM];
__device__ float g_ctx[SLEN*DM];
// pre-rounded (tf32-RNA) weight copies
__device__ float g_sqW[NBLK*DM*DM];
__device__ float g_skW[NBLK*DM*DM];
__device__ float g_svW[NBLK*DM*DM];
__device__ float g_soW[NBLK*DM*DM];
__device__ float g_cqW[NBLK*DM*DM];
__device__ float g_ckW[NBLK*DM*DM];
__device__ float g_cvW[NBLK*DM*DM];
__device__ float g_coW[NBLK*DM*DM];
__device__ float g_f1W[NBLK*DFFN*DM];
__device__ float g_f2W[NBLK*DM*DFFN];

// ---------------- helpers ----------------
__device__ __forceinline__ uint32_t f2tf(float x) {      // round-to-nearest tf32
    uint32_t r;
    asm("cvt.rna.tf32.f32 %0, %1;" : "=r"(r) : "f"(x));
    return r;
}
__device__ __forceinline__ float rndtf(float x) { return __uint_as_float(f2tf(x)); }
// raw bits; inputs are already tf32-rounded, so HW truncation is exact
__device__ __forceinline__ uint32_t f2r(float x) { return __float_as_uint(x); }

__device__ __forceinline__ uint32_t sptr(const void* p) {
    return (uint32_t)__cvta_generic_to_shared(p);
}
#define CPA16(dst, src) asm volatile("cp.async.cg.shared.global [%0],[%1],16;" :: "r"(dst), "l"(src))
#define CPCOMMIT()      asm volatile("cp.async.commit_group;")

__device__ __forceinline__ void mma_tf32(float* c, const uint32_t* a, uint32_t b0, uint32_t b1) {
    asm volatile(
        "mma.sync.aligned.m16n8k8.row.col.f32.tf32.tf32.f32 "
        "{%0,%1,%2,%3},{%4,%5,%6,%7},{%8,%9},{%0,%1,%2,%3};"
        : "+f"(c[0]), "+f"(c[1]), "+f"(c[2]), "+f"(c[3])
        : "r"(a[0]), "r"(a[1]), "r"(a[2]), "r"(a[3]), "r"(b0), "r"(b1));
}

// ---------------- tf32-RNA rounding copy (weights / ctx) ----------------
__global__ void round_tf_kernel(const float4* __restrict__ in, float4* __restrict__ out, int n4) {
    int i = blockIdx.x * blockDim.x + threadIdx.x;
    int stride = gridDim.x * blockDim.x;
    for (; i < n4; i += stride) {
        float4 v = in[i];
        v.x = rndtf(v.x); v.y = rndtf(v.y); v.z = rndtf(v.z); v.w = rndtf(v.w);
        out[i] = v;
    }
}

// ---------------- adaLN modulation GEMV (full fp32) ----------------
__global__ void mods_kernel(const float* __restrict__ t, const float* __restrict__ W,
                            const float* __restrict__ b, float* __restrict__ out) {
    int gw   = (blockIdx.x * blockDim.x + threadIdx.x) >> 5;
    int lane = threadIdx.x & 31;
    if (gw >= 6 * DM) return;
    const float* w = W + (size_t)gw * DM;
    float s = 0.f;
    for (int k = lane; k < DM; k += 32) s += t[k] * w[k];
    #pragma unroll
    for (int o = 16; o; o >>= 1) s += __shfl_xor_sync(0xffffffffu, s, o);
    if (lane == 0) out[gw] = s + b[gw];
}

// ---------------- LayerNorm (+ modulation); output tf32-rounded ----------------
__global__ void ln_kernel(const float* __restrict__ x, float* __restrict__ out,
                          const float* __restrict__ sc, const float* __restrict__ sh) {
    int row = blockIdx.x;
    const float* xr = x + (size_t)row * DM;
    float s = 0.f, s2 = 0.f;
    for (int c = threadIdx.x; c < DM; c += blockDim.x) {
        float v = xr[c]; s += v; s2 += v * v;
    }
    __shared__ float rs[8], rs2[8];
    int lane = threadIdx.x & 31, wid = threadIdx.x >> 5;
    #pragma unroll
    for (int o = 16; o; o >>= 1) {
        s  += __shfl_xor_sync(0xffffffffu, s,  o);
        s2 += __shfl_xor_sync(0xffffffffu, s2, o);
    }
    if (lane == 0) { rs[wid] = s; rs2[wid] = s2; }
    __syncthreads();
    float ts = 0.f, ts2 = 0.f;
    #pragma unroll
    for (int i = 0; i < 8; i++) { ts += rs[i]; ts2 += rs2[i]; }
    float mean = ts * (1.f / DM);
    float var  = ts2 * (1.f / DM) - mean * mean;
    float rstd = rsqrtf(var + 1e-6f);
    float* orow = out + (size_t)row * DM;
    for (int c = threadIdx.x; c < DM; c += blockDim.x) {
        float v = (xr[c] - mean) * rstd;
        if (sc) v = v * (1.f + sc[c]) + sh[c];
        orow[c] = rndtf(v);
    }
}

// ---------------- RoPE on q and k (in place); output tf32-rounded ----------------
__global__ void rope_kernel(float* __restrict__ q, float* __restrict__ k,
                            const float* __restrict__ rope) {
    int idx = blockIdx.x * blockDim.x + threadIdx.x;
    if (idx >= LQ * NH * 32) return;
    int e = idx & 31;
    int h = (idx >> 5) & (NH - 1);
    int l = idx >> 9;
    float r1 = rope[l * HDIM + e];
    float r2 = rope[l * HDIM + e + 32];
    float c1 = cosf(r1), s1 = sinf(r1);
    float c2 = cosf(r2), s2 = sinf(r2);
    size_t base = (size_t)l * DM + h * HDIM + e;
    float q1 = q[base], q2 = q[base + 32];
    q[base]      = rndtf(q1 * c1 - q2 * s1);
    q[base + 32] = rndtf(q2 * c2 + q1 * s2);
    float k1 = k[base], k2 = k[base + 32];
    k[base]      = rndtf(k1 * c1 - k2 * s1);
    k[base + 32] = rndtf(k2 * c2 + k1 * s2);
}

// ---------------- tf32 tensor-core GEMM ----------------
// C[M,N] = A[M,K] @ W[N,K]^T, 128x128x32 tiles, double-buffered cp.async
// A, W must be pre-rounded to tf32. epi: 0 = store rounded, 1 = GELU rounded,
// 2 = C += gate*(val+bias) (full fp32, residual stream)
#define GP 36   // smem pitch (floats) for 32-wide K tile

__device__ __forceinline__ void cp_tile128(const float* G, int ldg, int row0, int k0,
                                           float* S, int tid) {
    #pragma unroll
    for (int i = 0; i < 4; i++) {
        int id = tid + i * 256;
        int r = id >> 3, c4 = id & 7;
        CPA16(sptr(&S[r * GP + c4 * 4]), G + (size_t)(row0 + r) * ldg + k0 + c4 * 4);
    }
}

__global__ __launch_bounds__(256, 2) void gemm_tf32(
    int M, int N, int K,
    const float* __restrict__ A, const float* __restrict__ W,
    const float* __restrict__ bias, float* __restrict__ C,
    int epi, const float* __restrict__ gate) {
    extern __shared__ float sm[];
    float* As = sm;                    // 2 * 128 * GP
    float* Bs = sm + 2 * 128 * GP;     // 2 * 128 * GP
    int tid = threadIdx.x, wid = tid >> 5, lane = tid & 31;
    int tr = lane >> 2, tc = lane & 3;
    int m0 = blockIdx.y * 128, n0 = blockIdx.x * 128;
    int wm = (wid >> 2) * 64, wn = (wid & 3) * 32;

    float c[4][4][4];
    #pragma unroll
    for (int a = 0; a < 4; a++)
        #pragma unroll
        for (int b = 0; b < 4; b++)
            #pragma unroll
            for (int d = 0; d < 4; d++) c[a][b][d] = 0.f;

    int ntile = K / 32;
    cp_tile128(A, K, m0, 0, As, tid);
    cp_tile128(W, K, n0, 0, Bs, tid);
    CPCOMMIT();

    for (int kt = 0; kt < ntile; kt++) {
        if (kt + 1 < ntile) {
            cp_tile128(A, K, m0, (kt + 1) * 32, As + ((kt + 1) & 1) * 128 * GP, tid);
            cp_tile128(W, K, n0, (kt + 1) * 32, Bs + ((kt + 1) & 1) * 128 * GP, tid);
            CPCOMMIT();
            asm volatile("cp.async.wait_group 1;");
        } else {
            asm volatile("cp.async.wait_group 0;");
        }
        __syncthreads();
        const float* Ab = As + (kt & 1) * 128 * GP;
        const float* Bb = Bs + (kt & 1) * 128 * GP;
        #pragma unroll
        for (int ks = 0; ks < 4; ks++) {
            uint32_t af[4][4];
            #pragma unroll
            for (int mt = 0; mt < 4; mt++) {
                const float* ap = Ab + (wm + mt * 16) * GP + ks * 8;
                af[mt][0] = f2r(ap[tr * GP + tc]);
                af[mt][1] = f2r(ap[(tr + 8) * GP + tc]);
                af[mt][2] = f2r(ap[tr * GP + tc + 4]);
                af[mt][3] = f2r(ap[(tr + 8) * GP + tc + 4]);
            }
            #pragma unroll
            for (int nn = 0; nn < 4; nn++) {
                const float* bp = Bb + (wn + nn * 8) * GP + ks * 8;
                uint32_t b0 = f2r(bp[tr * GP + tc]);
                uint32_t b1 = f2r(bp[tr * GP + tc + 4]);
                #pragma unroll
                for (int mt = 0; mt < 4; mt++)
                    mma_tf32(c[mt][nn], af[mt], b0, b1);
            }
        }
        __syncthreads();
    }

    // epilogue
    #pragma unroll
    for (int mt = 0; mt < 4; mt++) {
        int r0 = m0 + wm + mt * 16 + tr;
        int r1 = r0 + 8;
        #pragma unroll
        for (int nn = 0; nn < 4; nn++) {
            int col = n0 + wn + nn * 8 + 2 * tc;
            float b0v = bias ? bias[col] : 0.f;
            float b1v = bias ? bias[col + 1] : 0.f;
            float v00 = c[mt][nn][0] + b0v, v01 = c[mt][nn][1] + b1v;
            float v10 = c[mt][nn][2] + b0v, v11 = c[mt][nn][3] + b1v;
            size_t i0 = (size_t)r0 * N + col;
            size_t i1 = (size_t)r1 * N + col;
            if (epi == 0) {
                C[i0] = rndtf(v00); C[i0 + 1] = rndtf(v01);
                C[i1] = rndtf(v10); C[i1 + 1] = rndtf(v11);
            } else if (epi == 1) {
                const float k = 0.70710678118654752f;
                C[i0]     = rndtf(0.5f * v00 * (1.f + erff(v00 * k)));
                C[i0 + 1] = rndtf(0.5f * v01 * (1.f + erff(v01 * k)));
                C[i1]     = rndtf(0.5f * v10 * (1.f + erff(v10 * k)));
                C[i1 + 1] = rndtf(0.5f * v11 * (1.f + erff(v11 * k)));
            } else {
                float g0 = gate ? gate[col] : 1.f;
                float g1 = gate ? gate[col + 1] : 1.f;
                C[i0]     += g0 * v00; C[i0 + 1] += g1 * v01;
                C[i1]     += g0 * v10; C[i1 + 1] += g1 * v11;
            }
        }
    }
}

// ---------------- tf32 tensor-core flash attention ----------------
// Inputs Q,K,V pre-rounded to tf32. Output rounded (feeds next GEMM A).
#define AP 68
__global__ __launch_bounds__(128, 3) void attn_mma(
    const float* __restrict__ Q, const float* __restrict__ K,
    const float* __restrict__ V, float* __restrict__ O,
    int Lk, float scale) {
    extern __shared__ float sm[];
    float* Qs = sm;
    float* Ks = Qs + 64 * AP;
    float* Vs = Ks + 64 * AP;
    float* Ps = Vs + 64 * AP;

    int tid = threadIdx.x, wid = tid >> 5, lane = tid & 31;
    int tr = lane >> 2, tc = lane & 3;
    int h = blockIdx.y, q0 = blockIdx.x * 64;
    const float* Qg = Q + (size_t)q0 * DM + h * HDIM;

    #pragma unroll
    for (int i = 0; i < 8; i++) {
        int id = tid + i * 128;
        int r = id >> 4, c4 = id & 15;
        CPA16(sptr(&Qs[r * AP + c4 * 4]), Qg + (size_t)r * DM + c4 * 4);
    }
    CPCOMMIT();
    asm volatile("cp.async.wait_group 0;");
    __syncthreads();

    // Q fragments (scale = 2^-3 multiply is exact on tf32-rounded values)
    uint32_t qf[8][4];
    #pragma unroll
    for (int ks = 0; ks < 8; ks++) {
        const float* qp = Qs + (wid * 16) * AP + ks * 8;
        qf[ks][0] = f2r(qp[tr * AP + tc] * scale);
        qf[ks][1] = f2r(qp[(tr + 8) * AP + tc] * scale);
        qf[ks][2] = f2r(qp[tr * AP + tc + 4] * scale);
        qf[ks][3] = f2r(qp[(tr + 8) * AP + tc + 4] * scale);
    }
    __syncthreads();

    float mv0 = -1e30f, mv1 = -1e30f, l0 = 0.f, l1 = 0.f;
    float o[8][4];
    #pragma unroll
    for (int nt = 0; nt < 8; nt++)
        #pragma unroll
        for (int d = 0; d < 4; d++) o[nt][d] = 0.f;

    for (int kv0 = 0; kv0 < Lk; kv0 += 64) {
        #pragma unroll
        for (int i = 0; i < 8; i++) {
            int id = tid + i * 128;
            int r = id >> 4, c4 = id & 15;
            const float* kg = K + (size_t)(kv0 + r) * DM + h * HDIM + c4 * 4;
            const float* vg = V + (size_t)(kv0 + r) * DM + h * HDIM + c4 * 4;
            CPA16(sptr(&Ks[r * AP + c4 * 4]), kg);
            CPA16(sptr(&Vs[r * AP + c4 * 4]), vg);
        }
        CPCOMMIT();
        asm volatile("cp.async.wait_group 0;");
        __syncthreads();

        // S = (Q*scale) @ K^T
        float s[8][4];
        #pragma unroll
        for (int nt = 0; nt < 8; nt++)
            #pragma unroll
            for (int d = 0; d < 4; d++) s[nt][d] = 0.f;
        #pragma unroll
        for (int ks = 0; ks < 8; ks++) {
            #pragma unroll
            for (int nt = 0; nt < 8; nt++) {
                uint32_t b0 = f2r(Ks[(nt * 8 + tr) * AP + ks * 8 + tc]);
                uint32_t b1 = f2r(Ks[(nt * 8 + tr) * AP + ks * 8 + tc + 4]);
                mma_tf32(s[nt], qf[ks], b0, b1);
            }
        }

        // online softmax (rows tr and tr+8 of this warp's 16)
        float ml0 = -1e30f, ml1 = -1e30f;
        #pragma unroll
        for (int nt = 0; nt < 8; nt++) {
            ml0 = fmaxf(ml0, fmaxf(s[nt][0], s[nt][1]));
            ml1 = fmaxf(ml1, fmaxf(s[nt][2], s[nt][3]));
        }
        ml0 = fmaxf(ml0, __shfl_xor_sync(0xffffffffu, ml0, 1));
        ml0 = fmaxf(ml0, __shfl_xor_sync(0xffffffffu, ml0, 2));
        ml1 = fmaxf(ml1, __shfl_xor_sync(0xffffffffu, ml1, 1));
        ml1 = fmaxf(ml1, __shfl_xor_sync(0xffffffffu, ml1, 2));
        float mn0 = fmaxf(mv0, ml0), mn1 = fmaxf(mv1, ml1);
        float cr0 = __expf(mv0 - mn0), cr1 = __expf(mv1 - mn1);
        float ls0 = 0.f, ls1 = 0.f;
        float* prow0 = &Ps[(wid * 16 + tr) * AP];
        float* prow1 = &Ps[(wid * 16 + tr + 8) * AP];
        #pragma unroll
        for (int nt = 0; nt < 8; nt++) {
            float p0 = __expf(s[nt][0] - mn0);
            float p1 = __expf(s[nt][1] - mn0);
            float p2 = __expf(s[nt][2] - mn1);
            float p3 = __expf(s[nt][3] - mn1);
            ls0 += p0 + p1; ls1 += p2 + p3;
            // store tf32-rounded so the PV mma can consume raw bits
            *(float2*)&prow0[nt * 8 + 2 * tc] = make_float2(rndtf(p0), rndtf(p1));
            *(float2*)&prow1[nt * 8 + 2 * tc] = make_float2(rndtf(p2), rndtf(p3));
        }
        ls0 += __shfl_xor_sync(0xffffffffu, ls0, 1);
        ls0 += __shfl_xor_sync(0xffffffffu, ls0, 2);
        ls1 += __shfl_xor_sync(0xffffffffu, ls1, 1);
        ls1 += __shfl_xor_sync(0xffffffffu, ls1, 2);
        l0 = l0 * cr0 + ls0;
        l1 = l1 * cr1 + ls1;
        mv0 = mn0; mv1 = mn1;
        #pragma unroll
        for (int nt = 0; nt < 8; nt++) {
            o[nt][0] *= cr0; o[nt][1] *= cr0;
            o[nt][2] *= cr1; o[nt][3] *= cr1;
        }
        __syncwarp();

        // O += P @ V
        #pragma unroll
        for (int ks = 0; ks < 8; ks++) {
            uint32_t af[4];
            const float* pp = Ps + (wid * 16) * AP + ks * 8;
            af[0] = f2r(pp[tr * AP + tc]);
            af[1] = f2r(pp[(tr + 8) * AP + tc]);
            af[2] = f2r(pp[tr * AP + tc + 4]);
            af[3] = f2r(pp[(tr + 8) * AP + tc + 4]);
            #pragma unroll
            for (int nt = 0; nt < 8; nt++) {
                uint32_t b0 = f2r(Vs[(ks * 8 + tc) * AP + nt * 8 + tr]);
                uint32_t b1 = f2r(Vs[(ks * 8 + tc + 4) * AP + nt * 8 + tr]);
                mma_tf32(o[nt], af, b0, b1);
            }
        }
        __syncthreads();
    }

    float i0 = 1.f / l0, i1 = 1.f / l1;
    float* og0 = O + (size_t)(q0 + wid * 16 + tr) * DM + h * HDIM;
    float* og1 = O + (size_t)(q0 + wid * 16 + tr + 8) * DM + h * HDIM;
    #pragma unroll
    for (int nt = 0; nt < 8; nt++) {
        *(float2*)&og0[nt * 8 + 2 * tc] =
            make_float2(rndtf(o[nt][0] * i0), rndtf(o[nt][1] * i0));
        *(float2*)&og1[nt * 8 + 2 * tc] =
            make_float2(rndtf(o[nt][2] * i1), rndtf(o[nt][3] * i1));
    }
}

// ---------------- host orchestration ----------------
extern "C" void kernel_launch(void* const* d_in, const int* in_sizes, int n_in,
                              void* d_out, int out_size) {
    const float* x    = (const float*)d_in[0];
    const float* temb = (const float*)d_in[1];
    const float* ctx  = (const float*)d_in[2];
    const float* rope = (const float*)d_in[3];
    const float* adaW = (const float*)d_in[4];
    const float* adab = (const float*)d_in[5];
    const float* sqW  = (const float*)d_in[6];
    const float* skW  = (const float*)d_in[7];
    const float* svW  = (const float*)d_in[8];
    const float* soW  = (const float*)d_in[9];
    const float* sob  = (const float*)d_in[10];
    const float* cqW  = (const float*)d_in[11];
    const float* ckW  = (const float*)d_in[12];
    const float* cvW  = (const float*)d_in[13];
    const float* coW  = (const float*)d_in[14];
    const float* cob  = (const float*)d_in[15];
    const float* f1W  = (const float*)d_in[16];
    const float* f1b  = (const float*)d_in[17];
    const float* f2W  = (const float*)d_in[18];
    const float* f2b  = (const float*)d_in[19];
    float* xo = (float*)d_out;

    float *hx, *q, *k, *v, *o, *mid, *mods, *ck, *cv, *rctx;
    float *rsq, *rsk, *rsv, *rso, *rcq, *rck, *rcv, *rco, *rf1, *rf2;
    cudaGetSymbolAddress((void**)&hx,   g_hx);
    cudaGetSymbolAddress((void**)&q,    g_q);
    cudaGetSymbolAddress((void**)&k,    g_k);
    cudaGetSymbolAddress((void**)&v,    g_v);
    cudaGetSymbolAddress((void**)&o,    g_o);
    cudaGetSymbolAddress((void**)&mid,  g_mid);
    cudaGetSymbolAddress((void**)&mods, g_mods);
    cudaGetSymbolAddress((void**)&ck,   g_ck);
    cudaGetSymbolAddress((void**)&cv,   g_cv);
    cudaGetSymbolAddress((void**)&rctx, g_ctx);
    cudaGetSymbolAddress((void**)&rsq,  g_sqW);
    cudaGetSymbolAddress((void**)&rsk,  g_skW);
    cudaGetSymbolAddress((void**)&rsv,  g_svW);
    cudaGetSymbolAddress((void**)&rso,  g_soW);
    cudaGetSymbolAddress((void**)&rcq,  g_cqW);
    cudaGetSymbolAddress((void**)&rck,  g_ckW);
    cudaGetSymbolAddress((void**)&rcv,  g_cvW);
    cudaGetSymbolAddress((void**)&rco,  g_coW);
    cudaGetSymbolAddress((void**)&rf1,  g_f1W);
    cudaGetSymbolAddress((void**)&rf2,  g_f2W);

    const int GEMM_SMEM = 2 * 2 * 128 * GP * (int)sizeof(float);   // 73728
    const int ATTN_SMEM = 4 * 64 * AP * (int)sizeof(float);        // 69632
    cudaFuncSetAttribute(gemm_tf32, cudaFuncAttributeMaxDynamicSharedMemorySize, GEMM_SMEM);
    cudaFuncSetAttribute(attn_mma,  cudaFuncAttributeMaxDynamicSharedMemorySize, ATTN_SMEM);

    cudaMemcpyAsync(xo, x, sizeof(float) * LQ * DM, cudaMemcpyDeviceToDevice);

    // pre-round weights + ctx to tf32 (RNA) once per launch
    const int RB = 256, RG = 1024;
    #define ROUND(dst, src, n) \
        round_tf_kernel<<<RG, RB>>>((const float4*)(src), (float4*)(dst), (n) / 4)
    ROUND(rsq, sqW, NBLK * DM * DM);
    ROUND(rsk, skW, NBLK * DM * DM);
    ROUND(rsv, svW, NBLK * DM * DM);
    ROUND(rso, soW, NBLK * DM * DM);
    ROUND(rcq, cqW, NBLK * DM * DM);
    ROUND(rck, ckW, NBLK * DM * DM);
    ROUND(rcv, cvW, NBLK * DM * DM);
    ROUND(rco, coW, NBLK * DM * DM);
    ROUND(rf1, f1W, NBLK * DFFN * DM);
    ROUND(rf2, f2W, NBLK * DM * DFFN);
    ROUND(rctx, ctx, SLEN * DM);
    #undef ROUND

    dim3 gD (DM / 128,   LQ / 128);
    dim3 gC (DM / 128,   SLEN / 128);
    dim3 gF1(DFFN / 128, LQ / 128);
    dim3 gA (LQ / 64, NH);

    for (int i = 0; i < NBLK; i++) {
        const float* adaWi = adaW + (size_t)i * 6 * DM * DM;
        const float* adabi = adab + (size_t)i * 6 * DM;
        const float* sqWi  = rsq  + (size_t)i * DM * DM;
        const float* skWi  = rsk  + (size_t)i * DM * DM;
        const float* svWi  = rsv  + (size_t)i * DM * DM;
        const float* soWi  = rso  + (size_t)i * DM * DM;
        const float* sobi  = sob  + (size_t)i * DM;
        const float* cqWi  = rcq  + (size_t)i * DM * DM;
        const float* ckWi  = rck  + (size_t)i * DM * DM;
        const float* cvWi  = rcv  + (size_t)i * DM * DM;
        const float* coWi  = rco  + (size_t)i * DM * DM;
        const float* cobi  = cob  + (size_t)i * DM;
        const float* f1Wi  = rf1  + (size_t)i * DFFN * DM;
        const float* f1bi  = f1b  + (size_t)i * DFFN;
        const float* f2Wi  = rf2  + (size_t)i * DM * DFFN;
        const float* f2bi  = f2b  + (size_t)i * DM;

        // adaLN mods (full fp32)
        mods_kernel<<<(6 * DM * 32 + 255) / 256, 256>>>(temb, adaWi, adabi, mods);
        // self-attn branch
        ln_kernel<<<LQ, 256>>>(xo, hx, mods + DM, mods);
        gemm_tf32<<<gD, 256, GEMM_SMEM>>>(LQ, DM, DM, hx, sqWi, nullptr, q, 0, nullptr);
        gemm_tf32<<<gD, 256, GEMM_SMEM>>>(LQ, DM, DM, hx, skWi, nullptr, k, 0, nullptr);
        gemm_tf32<<<gD, 256, GEMM_SMEM>>>(LQ, DM, DM, hx, svWi, nullptr, v, 0, nullptr);
        rope_kernel<<<(LQ * NH * 32 + 255) / 256, 256>>>(q, k, rope);
        attn_mma<<<gA, 128, ATTN_SMEM>>>(q, k, v, o, LQ, 0.125f);
        gemm_tf32<<<gD, 256, GEMM_SMEM>>>(LQ, DM, DM, o, soWi, sobi, xo, 2, mods + 2 * DM);
        // cross-attn branch
        ln_kernel<<<LQ, 256>>>(xo, hx, nullptr, nullptr);
        gemm_tf32<<<gD, 256, GEMM_SMEM>>>(LQ, DM, DM, hx, cqWi, nullptr, q, 0, nullptr);
        gemm_tf32<<<gC, 256, GEMM_SMEM>>>(SLEN, DM, DM, rctx, ckWi, nullptr, ck, 0, nullptr);
        gemm_tf32<<<gC, 256, GEMM_SMEM>>>(SLEN, DM, DM, rctx, cvWi, nullptr, cv, 0, nullptr);
        attn_mma<<<gA, 128, ATTN_SMEM>>>(q, ck, cv, o, SLEN, 0.125f);
        gemm_tf32<<<gD, 256, GEMM_SMEM>>>(LQ, DM, DM, o, coWi, cobi, xo, 2, nullptr);
        // MLP branch
        ln_kernel<<<LQ, 256>>>(xo, hx, mods + 4 * DM, mods + 3 * DM);
        gemm_tf32<<<gF1, 256, GEMM_SMEM>>>(LQ, DFFN, DM, hx, f1Wi, f1bi, mid, 1, nullptr);
        gemm_tf32<<<gD, 256, GEMM_SMEM>>>(LQ, DM, DFFN, mid, f2Wi, f2bi, xo, 2, mods + 5 * DM);
    }
}